// round 7
// baseline (speedup 1.0000x reference)
#include <cuda_runtime.h>

#define NN 100000
#define NE 1600000
#define NF 128
#define NH 64
#define NC 16

// ---------------- scratch (zero-initialized device globals; k_clear restores) ----------------
__device__ int   g_deg[2 * NN];             // [0,NN): out-degree, [NN,2NN): in-degree
__device__ int   g_rowptr[NN + 1];
__device__ int   g_cursor[NN];
__device__ int   g_col[NE];                 // src node per CSR slot
__device__ float g_h1[(size_t)NN * NH];     // (x@W1)*norm_src
__device__ float g_r[(size_t)NN * NH];      // relu(agg1*nd + b1)
__device__ float g_h2[(size_t)NN * NC];     // (r@W2)*norm_src

#define ADD2(acc, v) asm("add.rn.f32x2 %0, %0, %1;" : "+l"(acc) : "l"(v))
#define LDCG128(a, b, p) \
    asm("ld.global.cg.v2.u64 {%0, %1}, [%2];" : "=l"(a), "=l"(b) : "l"(p))
#define CP16(dst, src, sz) \
    asm volatile("cp.async.cg.shared.global [%0], [%1], 16, %2;" \
                 :: "r"(dst), "l"(src), "r"(sz))

__device__ __forceinline__ unsigned smem_u32(const void* p) {
    return (unsigned)__cvta_generic_to_shared(p);
}

// ---------------- degree histograms (both), 4 edges/thread ----------------
__global__ void k_hist(const int* __restrict__ src, const int* __restrict__ dst) {
    int i = blockIdx.x * blockDim.x + threadIdx.x;      // 400K threads
    if (i * 4 < NE) {
        int4 s = *(const int4*)&src[i * 4];
        int4 d = *(const int4*)&dst[i * 4];
        atomicAdd(&g_deg[s.x], 1);
        atomicAdd(&g_deg[s.y], 1);
        atomicAdd(&g_deg[s.z], 1);
        atomicAdd(&g_deg[s.w], 1);
        atomicAdd(&g_deg[NN + d.x], 1);
        atomicAdd(&g_deg[NN + d.y], 1);
        atomicAdd(&g_deg[NN + d.z], 1);
        atomicAdd(&g_deg[NN + d.w], 1);
    }
}

// ---------------- exclusive scan of in-degrees -> rowptr, cursor ----------------
__global__ void __launch_bounds__(1024) k_scan() {
    __shared__ int sblk[1024];
    const int t = threadIdx.x;
    const int CH = (NN + 1023) / 1024;   // 98
    int lo = min(t * CH, NN);
    int hi = min(lo + CH, NN);
    int s = 0;
    for (int i = lo; i < hi; i++) s += g_deg[NN + i];
    sblk[t] = s;
    __syncthreads();
    for (int off = 1; off < 1024; off <<= 1) {
        int u = (t >= off) ? sblk[t - off] : 0;
        __syncthreads();
        sblk[t] += u;
        __syncthreads();
    }
    int run = (t > 0) ? sblk[t - 1] : 0;
    for (int i = lo; i < hi; i++) {
        g_rowptr[i] = run;
        g_cursor[i] = run;
        run += g_deg[NN + i];
    }
    if (t == 1023) g_rowptr[NN] = sblk[1023];
}

// ---------------- fill CSR, 4 edges/thread ----------------
__global__ void k_fill(const int* __restrict__ src, const int* __restrict__ dst) {
    int i = blockIdx.x * blockDim.x + threadIdx.x;
    if (i * 4 < NE) {
        int4 s = *(const int4*)&src[i * 4];
        int4 d = *(const int4*)&dst[i * 4];
        int p0 = atomicAdd(&g_cursor[d.x], 1);
        int p1 = atomicAdd(&g_cursor[d.y], 1);
        int p2 = atomicAdd(&g_cursor[d.z], 1);
        int p3 = atomicAdd(&g_cursor[d.w], 1);
        g_col[p0] = s.x;
        g_col[p1] = s.y;
        g_col[p2] = s.z;
        g_col[p3] = s.w;
    }
}

// ---------------- layer-1 GEMM: h1 = (x @ W1) * norm_src ----------------
__global__ void __launch_bounds__(256) k_gemm1(const float* __restrict__ x,
                                               const float* __restrict__ W1) {
    __shared__ __align__(16) float Xs[2][256][20];  // node-major, 80B stride
    __shared__ __align__(16) float Ws[2][16][64];

    const int tid = threadIdx.x;
    const int tx = tid & 7;
    const int ty = tid >> 3;
    const int n0 = blockIdx.x * 256;
    const int wkk = tid >> 4, wf4 = tid & 15;

    unsigned long long accp[8][4];
    #pragma unroll
    for (int i = 0; i < 8; i++)
        #pragma unroll
        for (int j = 0; j < 4; j++) accp[i][j] = 0ull;

    auto issue = [&](int kc) {
        int buf = kc & 1;
        #pragma unroll
        for (int it = 0; it < 4; it++) {
            int i = tid + it * 256;
            int nl = i >> 2, f4 = i & 3;
            int n = n0 + nl;
            unsigned d = smem_u32(&Xs[buf][nl][f4 * 4]);
            const float* s = &x[(size_t)n * NF + kc * 16 + f4 * 4];
            CP16(d, s, (n < NN) ? 16 : 0);
        }
        unsigned dw = smem_u32(&Ws[buf][wkk][wf4 * 4]);
        const float* sw = &W1[(size_t)(kc * 16 + wkk) * NH + wf4 * 4];
        CP16(dw, sw, 16);
        asm volatile("cp.async.commit_group;");
    };

    issue(0);
    for (int kc = 0; kc < NF / 16; kc++) {
        if (kc + 1 < NF / 16) {
            issue(kc + 1);
            asm volatile("cp.async.wait_group 1;");
        } else {
            asm volatile("cp.async.wait_group 0;");
        }
        __syncthreads();
        const int buf = kc & 1;

        #pragma unroll
        for (int kk = 0; kk < 16; kk++) {
            float av[8];
            #pragma unroll
            for (int i = 0; i < 8; i++) av[i] = Xs[buf][ty * 8 + i][kk];
            ulonglong2 w0 = *(const ulonglong2*)&Ws[buf][kk][tx * 8];
            ulonglong2 w1 = *(const ulonglong2*)&Ws[buf][kk][tx * 8 + 4];
            unsigned long long bp[4] = {w0.x, w0.y, w1.x, w1.y};
            #pragma unroll
            for (int i = 0; i < 8; i++) {
                unsigned long long ad;
                asm("mov.b64 %0, {%1, %1};" : "=l"(ad) : "f"(av[i]));
                #pragma unroll
                for (int jj = 0; jj < 4; jj++)
                    asm("fma.rn.f32x2 %0, %1, %2, %0;"
                        : "+l"(accp[i][jj]) : "l"(ad), "l"(bp[jj]));
            }
        }
        __syncthreads();
    }

    #pragma unroll
    for (int i = 0; i < 8; i++) {
        int n = n0 + ty * 8 + i;
        if (n < NN) {
            float s = rsqrtf((float)max(g_deg[n], 1));
            float o[8];
            #pragma unroll
            for (int jj = 0; jj < 4; jj++) {
                float lo, hi;
                asm("mov.b64 {%0, %1}, %2;" : "=f"(lo), "=f"(hi) : "l"(accp[i][jj]));
                o[2 * jj] = lo * s;
                o[2 * jj + 1] = hi * s;
            }
            *(float4*)&g_h1[(size_t)n * NH + tx * 8] = make_float4(o[0], o[1], o[2], o[3]);
            *(float4*)&g_h1[(size_t)n * NH + tx * 8 + 4] = make_float4(o[4], o[5], o[6], o[7]);
        }
    }
}

// ---------------- layer-1 gather: r = relu(sum h1[src] * nd + b1) ----------------
__global__ void __launch_bounds__(256) k_gather1(const float* __restrict__ b1) {
    const int g = blockIdx.x * 16 + (threadIdx.x >> 4);
    const int lane = threadIdx.x & 15;

    const int s0 = g_rowptr[g];
    const int s1 = g_rowptr[g + 1];
    unsigned long long acc0 = 0ull, acc1 = 0ull;

    int j = s0;
    for (; j + 8 <= s1; j += 8) {
        int c[8];
        #pragma unroll
        for (int q = 0; q < 8; q++) c[q] = __ldg(&g_col[j + q]);
        #pragma unroll
        for (int q = 0; q < 8; q++) {
            unsigned long long a, b;
            LDCG128(a, b, &g_h1[(size_t)c[q] * NH + lane * 4]);
            ADD2(acc0, a);
            ADD2(acc1, b);
        }
    }
    for (; j < s1; j++) {
        int c = __ldg(&g_col[j]);
        unsigned long long a, b;
        LDCG128(a, b, &g_h1[(size_t)c * NH + lane * 4]);
        ADD2(acc0, a);
        ADD2(acc1, b);
    }

    float nd = rsqrtf((float)max(s1 - s0, 1));
    float a0, a1, a2, a3;
    asm("mov.b64 {%0, %1}, %2;" : "=f"(a0), "=f"(a1) : "l"(acc0));
    asm("mov.b64 {%0, %1}, %2;" : "=f"(a2), "=f"(a3) : "l"(acc1));
    float4 bb = *(const float4*)&b1[lane * 4];
    float4 r;
    r.x = fmaxf(fmaf(a0, nd, bb.x), 0.f);
    r.y = fmaxf(fmaf(a1, nd, bb.y), 0.f);
    r.z = fmaxf(fmaf(a2, nd, bb.z), 0.f);
    r.w = fmaxf(fmaf(a3, nd, bb.w), 0.f);
    *(float4*)&g_r[(size_t)g * NH + lane * 4] = r;
}

// ---------------- hidden GEMM: h2 = (r @ W2) * norm_src ----------------
__global__ void __launch_bounds__(256) k_hidden(const float* __restrict__ W2) {
    __shared__ __align__(16) float R[16][NH + 4];
    __shared__ __align__(16) float W2s[NH * NC];

    const int n0 = blockIdx.x * 16;
    const int tid = threadIdx.x;

    *(float4*)&W2s[tid * 4] = *(const float4*)&W2[tid * 4];
    {
        int i = tid * 4;
        int nl = i >> 6;
        int k = i & 63;
        float4 v = *(const float4*)&g_r[(size_t)(n0 + nl) * NH + k];
        R[nl][k + 0] = v.x;
        R[nl][k + 1] = v.y;
        R[nl][k + 2] = v.z;
        R[nl][k + 3] = v.w;
    }
    __syncthreads();

    const int nl = tid >> 4;
    const int cl = tid & 15;
    const int n = n0 + nl;
    float acc = 0.f;
    #pragma unroll
    for (int k = 0; k < NH; k++)
        acc = fmaf(R[nl][k], W2s[k * NC + cl], acc);
    g_h2[(size_t)n * NC + cl] = acc * rsqrtf((float)max(g_deg[n], 1));
}

// ---------------- layer-2 gather + log_softmax fused ----------------
__global__ void __launch_bounds__(256) k_gather2(const float* __restrict__ b2,
                                                 float* __restrict__ out) {
    int g0 = blockIdx.x * 64 + (threadIdx.x >> 2);
    const bool valid = (g0 < NN);
    const int g = valid ? g0 : (NN - 1);
    const int lane = threadIdx.x & 3;

    const int s0 = g_rowptr[g];
    const int s1 = g_rowptr[g + 1];
    unsigned long long acc0 = 0ull, acc1 = 0ull;

    int j = s0;
    for (; j + 8 <= s1; j += 8) {
        int c[8];
        #pragma unroll
        for (int q = 0; q < 8; q++) c[q] = __ldg(&g_col[j + q]);
        #pragma unroll
        for (int q = 0; q < 8; q++) {
            unsigned long long a, b;
            LDCG128(a, b, &g_h2[(size_t)c[q] * NC + lane * 4]);
            ADD2(acc0, a);
            ADD2(acc1, b);
        }
    }
    for (; j < s1; j++) {
        int c = __ldg(&g_col[j]);
        unsigned long long a, b;
        LDCG128(a, b, &g_h2[(size_t)c * NC + lane * 4]);
        ADD2(acc0, a);
        ADD2(acc1, b);
    }

    float nd = rsqrtf((float)max(s1 - s0, 1));
    float v[4];
    asm("mov.b64 {%0, %1}, %2;" : "=f"(v[0]), "=f"(v[1]) : "l"(acc0));
    asm("mov.b64 {%0, %1}, %2;" : "=f"(v[2]), "=f"(v[3]) : "l"(acc1));
    float4 bb = *(const float4*)&b2[lane * 4];
    v[0] = fmaf(v[0], nd, bb.x);
    v[1] = fmaf(v[1], nd, bb.y);
    v[2] = fmaf(v[2], nd, bb.z);
    v[3] = fmaf(v[3], nd, bb.w);

    float mloc = fmaxf(fmaxf(v[0], v[1]), fmaxf(v[2], v[3]));
    mloc = fmaxf(mloc, __shfl_xor_sync(0xFFFFFFFFu, mloc, 1, 4));
    mloc = fmaxf(mloc, __shfl_xor_sync(0xFFFFFFFFu, mloc, 2, 4));

    float sl = __expf(v[0] - mloc) + __expf(v[1] - mloc) +
               __expf(v[2] - mloc) + __expf(v[3] - mloc);
    sl += __shfl_xor_sync(0xFFFFFFFFu, sl, 1, 4);
    sl += __shfl_xor_sync(0xFFFFFFFFu, sl, 2, 4);
    float l = mloc + __logf(sl);

    if (valid)
        *(float4*)&out[(size_t)g * NC + lane * 4] =
            make_float4(v[0] - l, v[1] - l, v[2] - l, v[3] - l);
}

// ---------------- clear degrees for the next invocation ----------------
__global__ void k_clear() {
    int i = blockIdx.x * blockDim.x + threadIdx.x;
    if (i * 4 < 2 * NN) *(int4*)&g_deg[i * 4] = make_int4(0, 0, 0, 0);
}

// ---------------- launch ----------------
extern "C" void kernel_launch(void* const* d_in, const int* in_sizes, int n_in,
                              void* d_out, int out_size) {
    const float* x   = (const float*)d_in[0];
    const int*   src = (const int*)d_in[1];
    const int*   dst = (const int*)d_in[2];
    const float* W1  = (const float*)d_in[3];
    const float* b1  = (const float*)d_in[4];
    const float* W2  = (const float*)d_in[5];
    const float* b2  = (const float*)d_in[6];
    float* out = (float*)d_out;

    k_hist<<<(NE / 4 + 255) / 256, 256>>>(src, dst);      // 1
    k_scan<<<1, 1024>>>();                                // 2
    k_fill<<<(NE / 4 + 255) / 256, 256>>>(src, dst);      // 3
    k_gemm1<<<(NN + 255) / 256, 256>>>(x, W1);            // 4
    k_gather1<<<NN / 16, 256>>>(b1);                      // 5  <- profiled
    k_hidden<<<NN / 16, 256>>>(W2);                       // 6
    k_gather2<<<(NN + 63) / 64, 256>>>(b2, out);          // 7
    k_clear<<<(2 * NN / 4 + 255) / 256, 256>>>();         // 8 (restore state)
}

// round 9
// speedup vs baseline: 1.7735x; 1.7735x over previous
#include <cuda_runtime.h>

#define NN 100000
#define NE 1600000
#define NF 128
#define NH 64
#define NC 16

// ---------------- scratch (static device globals) ----------------
__device__ int   g_deg[2 * NN];             // [0,NN): out-degree, [NN,2NN): in-degree
__device__ int   g_part[256];               // scan partials (196 used)
__device__ int   g_rowptr[NN + 1];
__device__ int   g_cursor[NN];
__device__ int   g_col[NE];                 // src node per CSR slot
__device__ float g_h1[(size_t)NN * NH];     // (x@W1)*norm_src
__device__ float g_r[(size_t)NN * NH];      // relu(agg1*nd + b1)
__device__ float g_h2[(size_t)NN * NC];     // (r@W2)*norm_src

#define ADD2(acc, v) asm("add.rn.f32x2 %0, %0, %1;" : "+l"(acc) : "l"(v))
#define CP16(dst, src, sz) \
    asm volatile("cp.async.cg.shared.global [%0], [%1], 16, %2;" \
                 :: "r"(dst), "l"(src), "r"(sz))

__device__ __forceinline__ unsigned smem_u32(const void* p) {
    return (unsigned)__cvta_generic_to_shared(p);
}

// ---------------- in-degree histogram ----------------
__global__ void k_hist(const int* __restrict__ dst) {
    int i = blockIdx.x * blockDim.x + threadIdx.x;
    if (i < NE) atomicAdd(&g_deg[NN + dst[i]], 1);
}

// ---------------- scan phase A: 196 blocks x 512 nodes -> block sums ----------------
__global__ void __launch_bounds__(256) k_scanA() {
    __shared__ int sh[256];
    const int t = threadIdx.x;
    int i0 = blockIdx.x * 512 + 2 * t;
    int s = 0;
    if (i0 < NN) s += g_deg[NN + i0];
    if (i0 + 1 < NN) s += g_deg[NN + i0 + 1];
    sh[t] = s;
    __syncthreads();
    for (int off = 128; off > 0; off >>= 1) {
        if (t < off) sh[t] += sh[t + off];
        __syncthreads();
    }
    if (t == 0) g_part[blockIdx.x] = sh[0];
    if (t == 1 && blockIdx.x == 0) g_rowptr[NN] = NE;
}

// ---------------- scan phase C: every block scans partials + local scan ----------------
__global__ void __launch_bounds__(256) k_scanC() {
    __shared__ int part[256];
    __shared__ int loc[256];
    const int t = threadIdx.x;
    const int b = blockIdx.x;

    part[t] = (t < 196) ? g_part[t] : 0;
    __syncthreads();
    for (int off = 1; off < 256; off <<= 1) {
        int u = (t >= off) ? part[t - off] : 0;
        __syncthreads();
        part[t] += u;
        __syncthreads();
    }
    int offset = (b > 0) ? part[b - 1] : 0;

    int i0 = b * 512 + 2 * t;
    int d0 = (i0 < NN) ? g_deg[NN + i0] : 0;
    int d1 = (i0 + 1 < NN) ? g_deg[NN + i0 + 1] : 0;
    loc[t] = d0 + d1;
    __syncthreads();
    for (int off = 1; off < 256; off <<= 1) {
        int u = (t >= off) ? loc[t - off] : 0;
        __syncthreads();
        loc[t] += u;
        __syncthreads();
    }
    int excl = offset + ((t > 0) ? loc[t - 1] : 0);
    if (i0 < NN)     { g_rowptr[i0] = excl;          g_cursor[i0] = excl; }
    if (i0 + 1 < NN) { g_rowptr[i0 + 1] = excl + d0; g_cursor[i0 + 1] = excl + d0; }
}

// ---------------- fill CSR + out-degree ----------------
__global__ void k_fill(const int* __restrict__ src, const int* __restrict__ dst) {
    int e = blockIdx.x * blockDim.x + threadIdx.x;
    if (e < NE) {
        int d = dst[e];
        int s = src[e];
        int pos = atomicAdd(&g_cursor[d], 1);
        g_col[pos] = s;
        atomicAdd(&g_deg[s], 1);
    }
}

// ---------------- layer-1 GEMM: h1 = (x @ W1) * norm_src ----------------
// 128 nodes x 64 feats/block; 256 threads, 4 nodes x 8 feats each.
// X double-buffered cp.async, row stride 20 floats (80B, 16B-aligned),
// 16B chunks XOR-swizzled by (row>>2)&3 -> conflict-free LDS.
#define XS_STRIDE 20
#define XS_ROWS 128

__global__ void __launch_bounds__(256, 2) k_gemm1(const float* __restrict__ x,
                                                  const float* __restrict__ W1) {
    __shared__ __align__(16) float Xs[2][XS_ROWS][XS_STRIDE];  // 20.5KB
    __shared__ __align__(16) float Ws[2][16][64];              // 8KB

    const int tid = threadIdx.x;
    const int tx = tid & 7;     // feat group (8 feats)
    const int ty = tid >> 3;    // node group (4 nodes), 0..31
    const int n0 = blockIdx.x * XS_ROWS;
    const int wk = tid >> 4, wf4 = tid & 15;

    unsigned long long accp[4][4];
    #pragma unroll
    for (int i = 0; i < 4; i++)
        #pragma unroll
        for (int j = 0; j < 4; j++) accp[i][j] = 0ull;

    auto issue = [&](int kc) {
        const int buf = kc & 1;
        #pragma unroll
        for (int it = 0; it < 2; it++) {
            int i = tid + it * 256;          // 0..511 chunk index
            int nl = i >> 2, c = i & 3;
            int n = n0 + nl;
            int cs = c ^ ((nl >> 2) & 3);    // swizzled chunk slot
            unsigned d = smem_u32(&Xs[buf][nl][cs * 4]);
            const float* s = &x[(size_t)n * NF + kc * 16 + c * 4];
            CP16(d, s, (n < NN) ? 16 : 0);
        }
        unsigned dw = smem_u32(&Ws[buf][wk][wf4 * 4]);
        const float* sw = &W1[(size_t)(kc * 16 + wk) * NH + wf4 * 4];
        CP16(dw, sw, 16);
        asm volatile("cp.async.commit_group;");
    };

    issue(0);
    for (int kc = 0; kc < NF / 16; kc++) {
        if (kc + 1 < NF / 16) {
            issue(kc + 1);
            asm volatile("cp.async.wait_group 1;");
        } else {
            asm volatile("cp.async.wait_group 0;");
        }
        __syncthreads();
        const int buf = kc & 1;
        const int swz = ty & 3;

        #pragma unroll
        for (int kk = 0; kk < 16; kk++) {
            const int col = ((((kk >> 2) ^ swz) << 2) | (kk & 3));
            float av[4];
            #pragma unroll
            for (int i = 0; i < 4; i++) av[i] = Xs[buf][ty * 4 + i][col];
            ulonglong2 w0 = *(const ulonglong2*)&Ws[buf][kk][tx * 8];
            ulonglong2 w1 = *(const ulonglong2*)&Ws[buf][kk][tx * 8 + 4];
            unsigned long long bp[4] = {w0.x, w0.y, w1.x, w1.y};
            #pragma unroll
            for (int i = 0; i < 4; i++) {
                unsigned long long ad;
                asm("mov.b64 %0, {%1, %1};" : "=l"(ad) : "f"(av[i]));
                #pragma unroll
                for (int jj = 0; jj < 4; jj++)
                    asm("fma.rn.f32x2 %0, %1, %2, %0;"
                        : "+l"(accp[i][jj]) : "l"(ad), "l"(bp[jj]));
            }
        }
        __syncthreads();
    }

    #pragma unroll
    for (int i = 0; i < 4; i++) {
        int n = n0 + ty * 4 + i;
        if (n < NN) {
            float s = rsqrtf((float)max(g_deg[n], 1));   // norm_src
            float o[8];
            #pragma unroll
            for (int jj = 0; jj < 4; jj++) {
                float lo, hi;
                asm("mov.b64 {%0, %1}, %2;" : "=f"(lo), "=f"(hi) : "l"(accp[i][jj]));
                o[2 * jj] = lo * s;
                o[2 * jj + 1] = hi * s;
            }
            *(float4*)&g_h1[(size_t)n * NH + tx * 8] = make_float4(o[0], o[1], o[2], o[3]);
            *(float4*)&g_h1[(size_t)n * NH + tx * 8 + 4] = make_float4(o[4], o[5], o[6], o[7]);
        }
    }
}

// ---------------- layer-1 gather: r = relu(sum h1[src] * nd + b1) ----------------
// 16 lanes/node, 1 float4 each; unroll 8 -> 8 LDG.128 in flight per lane.
__global__ void __launch_bounds__(256) k_gather1(const float* __restrict__ b1) {
    const int g = blockIdx.x * 16 + (threadIdx.x >> 4);
    const int lane = threadIdx.x & 15;

    const int s0 = g_rowptr[g];
    const int s1 = g_rowptr[g + 1];
    unsigned long long acc0 = 0ull, acc1 = 0ull;

    int j = s0;
    for (; j + 8 <= s1; j += 8) {
        int c[8];
        #pragma unroll
        for (int q = 0; q < 8; q++) c[q] = __ldg(&g_col[j + q]);
        #pragma unroll
        for (int q = 0; q < 8; q++) {
            ulonglong2 v = *(const ulonglong2*)&g_h1[(size_t)c[q] * NH + lane * 4];
            ADD2(acc0, v.x);
            ADD2(acc1, v.y);
        }
    }
    for (; j < s1; j++) {
        int c = __ldg(&g_col[j]);
        ulonglong2 v = *(const ulonglong2*)&g_h1[(size_t)c * NH + lane * 4];
        ADD2(acc0, v.x);
        ADD2(acc1, v.y);
    }

    float nd = rsqrtf((float)max(s1 - s0, 1));   // norm_dst
    float a0, a1, a2, a3;
    asm("mov.b64 {%0, %1}, %2;" : "=f"(a0), "=f"(a1) : "l"(acc0));
    asm("mov.b64 {%0, %1}, %2;" : "=f"(a2), "=f"(a3) : "l"(acc1));
    float4 bb = *(const float4*)&b1[lane * 4];
    float4 r;
    r.x = fmaxf(fmaf(a0, nd, bb.x), 0.f);
    r.y = fmaxf(fmaf(a1, nd, bb.y), 0.f);
    r.z = fmaxf(fmaf(a2, nd, bb.z), 0.f);
    r.w = fmaxf(fmaf(a3, nd, bb.w), 0.f);
    *(float4*)&g_r[(size_t)g * NH + lane * 4] = r;
}

// ---------------- hidden GEMM: h2 = (r @ W2) * norm_src ----------------
__global__ void __launch_bounds__(256) k_hidden(const float* __restrict__ W2) {
    __shared__ __align__(16) float R[16][NH + 4];
    __shared__ __align__(16) float W2s[NH * NC];

    const int n0 = blockIdx.x * 16;
    const int tid = threadIdx.x;

    *(float4*)&W2s[tid * 4] = *(const float4*)&W2[tid * 4];
    {
        int i = tid * 4;
        int nl = i >> 6;
        int k = i & 63;
        float4 v = *(const float4*)&g_r[(size_t)(n0 + nl) * NH + k];
        R[nl][k + 0] = v.x;
        R[nl][k + 1] = v.y;
        R[nl][k + 2] = v.z;
        R[nl][k + 3] = v.w;
    }
    __syncthreads();

    const int nl = tid >> 4;
    const int cl = tid & 15;
    const int n = n0 + nl;
    float acc = 0.f;
    #pragma unroll
    for (int k = 0; k < NH; k++)
        acc = fmaf(R[nl][k], W2s[k * NC + cl], acc);
    g_h2[(size_t)n * NC + cl] = acc * rsqrtf((float)max(g_deg[n], 1));
}

// ---------------- layer-2 gather + log_softmax fused ----------------
// 4 lanes/node, 1 float4 (4 classes) each; unroll 8.
__global__ void __launch_bounds__(256) k_gather2(const float* __restrict__ b2,
                                                 float* __restrict__ out) {
    int g0 = blockIdx.x * 64 + (threadIdx.x >> 2);
    const bool valid = (g0 < NN);
    const int g = valid ? g0 : (NN - 1);
    const int lane = threadIdx.x & 3;

    const int s0 = g_rowptr[g];
    const int s1 = g_rowptr[g + 1];
    unsigned long long acc0 = 0ull, acc1 = 0ull;

    int j = s0;
    for (; j + 8 <= s1; j += 8) {
        int c[8];
        #pragma unroll
        for (int q = 0; q < 8; q++) c[q] = __ldg(&g_col[j + q]);
        #pragma unroll
        for (int q = 0; q < 8; q++) {
            ulonglong2 v = *(const ulonglong2*)&g_h2[(size_t)c[q] * NC + lane * 4];
            ADD2(acc0, v.x);
            ADD2(acc1, v.y);
        }
    }
    for (; j < s1; j++) {
        int c = __ldg(&g_col[j]);
        ulonglong2 v = *(const ulonglong2*)&g_h2[(size_t)c * NC + lane * 4];
        ADD2(acc0, v.x);
        ADD2(acc1, v.y);
    }

    float nd = rsqrtf((float)max(s1 - s0, 1));
    float v[4];
    asm("mov.b64 {%0, %1}, %2;" : "=f"(v[0]), "=f"(v[1]) : "l"(acc0));
    asm("mov.b64 {%0, %1}, %2;" : "=f"(v[2]), "=f"(v[3]) : "l"(acc1));
    float4 bb = *(const float4*)&b2[lane * 4];
    v[0] = fmaf(v[0], nd, bb.x);
    v[1] = fmaf(v[1], nd, bb.y);
    v[2] = fmaf(v[2], nd, bb.z);
    v[3] = fmaf(v[3], nd, bb.w);

    float mloc = fmaxf(fmaxf(v[0], v[1]), fmaxf(v[2], v[3]));
    mloc = fmaxf(mloc, __shfl_xor_sync(0xFFFFFFFFu, mloc, 1, 4));
    mloc = fmaxf(mloc, __shfl_xor_sync(0xFFFFFFFFu, mloc, 2, 4));

    float sl = __expf(v[0] - mloc) + __expf(v[1] - mloc) +
               __expf(v[2] - mloc) + __expf(v[3] - mloc);
    sl += __shfl_xor_sync(0xFFFFFFFFu, sl, 1, 4);
    sl += __shfl_xor_sync(0xFFFFFFFFu, sl, 2, 4);
    float l = mloc + __logf(sl);

    if (valid)
        *(float4*)&out[(size_t)g * NC + lane * 4] =
            make_float4(v[0] - l, v[1] - l, v[2] - l, v[3] - l);
}

// ---------------- launch ----------------
extern "C" void kernel_launch(void* const* d_in, const int* in_sizes, int n_in,
                              void* d_out, int out_size) {
    const float* x   = (const float*)d_in[0];
    const int*   src = (const int*)d_in[1];
    const int*   dst = (const int*)d_in[2];
    const float* W1  = (const float*)d_in[3];
    const float* b1  = (const float*)d_in[4];
    const float* W2  = (const float*)d_in[5];
    const float* b2  = (const float*)d_in[6];
    float* out = (float*)d_out;

    void* pdeg;
    cudaGetSymbolAddress(&pdeg, g_deg);
    cudaMemsetAsync(pdeg, 0, (size_t)2 * NN * sizeof(int));

    k_hist<<<(NE + 255) / 256, 256>>>(dst);
    k_scanA<<<196, 256>>>();
    k_scanC<<<196, 256>>>();
    k_fill<<<(NE + 255) / 256, 256>>>(src, dst);
    k_gemm1<<<(NN + 127) / 128, 256>>>(x, W1);
    k_gather1<<<NN / 16, 256>>>(b1);
    k_hidden<<<NN / 16, 256>>>(W2);
    k_gather2<<<(NN + 63) / 64, 256>>>(b2, out);
}

// round 10
// speedup vs baseline: 2.1557x; 1.2155x over previous
#include <cuda_runtime.h>
#include <cuda_fp16.h>

#define NN 100000
#define NE 1600000
#define NF 128
#define NH 64
#define NC 16

// ---------------- scratch (static device globals) ----------------
__device__ int    g_deg[2 * NN];            // [0,NN): out-degree, [NN,2NN): in-degree
__device__ int    g_part[256];              // scan partials (196 used)
__device__ int    g_rowptr[NN + 1];
__device__ int    g_cursor[NN];
__device__ int    g_col[NE];                // src node per CSR slot
__device__ __half g_h1h[(size_t)NN * NH];   // (x@W1)*norm_src, fp16
__device__ float  g_h2[(size_t)NN * NC];    // (r@W2)*norm_src

#define ADD2(acc, v) asm("add.rn.f32x2 %0, %0, %1;" : "+l"(acc) : "l"(v))
#define CP16(dst, src, sz) \
    asm volatile("cp.async.cg.shared.global [%0], [%1], 16, %2;" \
                 :: "r"(dst), "l"(src), "r"(sz))

__device__ __forceinline__ unsigned smem_u32(const void* p) {
    return (unsigned)__cvta_generic_to_shared(p);
}

// ---------------- in-degree histogram ----------------
__global__ void k_hist(const int* __restrict__ dst) {
    int i = blockIdx.x * blockDim.x + threadIdx.x;
    if (i < NE) atomicAdd(&g_deg[NN + dst[i]], 1);
}

// ---------------- scan phase A: 196 blocks x 512 nodes -> block sums ----------------
__global__ void __launch_bounds__(256) k_scanA() {
    __shared__ int sh[256];
    const int t = threadIdx.x;
    int i0 = blockIdx.x * 512 + 2 * t;
    int s = 0;
    if (i0 < NN) s += g_deg[NN + i0];
    if (i0 + 1 < NN) s += g_deg[NN + i0 + 1];
    sh[t] = s;
    __syncthreads();
    for (int off = 128; off > 0; off >>= 1) {
        if (t < off) sh[t] += sh[t + off];
        __syncthreads();
    }
    if (t == 0) g_part[blockIdx.x] = sh[0];
    if (t == 1 && blockIdx.x == 0) g_rowptr[NN] = NE;
}

// ---------------- scan phase C: every block scans partials + local scan ----------------
__global__ void __launch_bounds__(256) k_scanC() {
    __shared__ int part[256];
    __shared__ int loc[256];
    const int t = threadIdx.x;
    const int b = blockIdx.x;

    part[t] = (t < 196) ? g_part[t] : 0;
    __syncthreads();
    for (int off = 1; off < 256; off <<= 1) {
        int u = (t >= off) ? part[t - off] : 0;
        __syncthreads();
        part[t] += u;
        __syncthreads();
    }
    int offset = (b > 0) ? part[b - 1] : 0;

    int i0 = b * 512 + 2 * t;
    int d0 = (i0 < NN) ? g_deg[NN + i0] : 0;
    int d1 = (i0 + 1 < NN) ? g_deg[NN + i0 + 1] : 0;
    loc[t] = d0 + d1;
    __syncthreads();
    for (int off = 1; off < 256; off <<= 1) {
        int u = (t >= off) ? loc[t - off] : 0;
        __syncthreads();
        loc[t] += u;
        __syncthreads();
    }
    int excl = offset + ((t > 0) ? loc[t - 1] : 0);
    if (i0 < NN)     { g_rowptr[i0] = excl;          g_cursor[i0] = excl; }
    if (i0 + 1 < NN) { g_rowptr[i0 + 1] = excl + d0; g_cursor[i0 + 1] = excl + d0; }
}

// ---------------- fill CSR + out-degree ----------------
__global__ void k_fill(const int* __restrict__ src, const int* __restrict__ dst) {
    int e = blockIdx.x * blockDim.x + threadIdx.x;
    if (e < NE) {
        int d = dst[e];
        int s = src[e];
        int pos = atomicAdd(&g_cursor[d], 1);
        g_col[pos] = s;
        atomicAdd(&g_deg[s], 1);
    }
}

// ---------------- layer-1 GEMM: h1h = fp16((x @ W1) * norm_src) ----------------
// R6-exact structure: 256 nodes x 64 feats/block, cp.async double-buffered.
__global__ void __launch_bounds__(256) k_gemm1(const float* __restrict__ x,
                                               const float* __restrict__ W1) {
    __shared__ __align__(16) float Xs[2][256][20];  // node-major, 80B stride
    __shared__ __align__(16) float Ws[2][16][64];

    const int tid = threadIdx.x;
    const int tx = tid & 7;
    const int ty = tid >> 3;
    const int n0 = blockIdx.x * 256;
    const int wkk = tid >> 4, wf4 = tid & 15;

    unsigned long long accp[8][4];
    #pragma unroll
    for (int i = 0; i < 8; i++)
        #pragma unroll
        for (int j = 0; j < 4; j++) accp[i][j] = 0ull;

    auto issue = [&](int kc) {
        int buf = kc & 1;
        #pragma unroll
        for (int it = 0; it < 4; it++) {
            int i = tid + it * 256;
            int nl = i >> 2, f4 = i & 3;
            int n = n0 + nl;
            unsigned d = smem_u32(&Xs[buf][nl][f4 * 4]);
            const float* s = &x[(size_t)n * NF + kc * 16 + f4 * 4];
            CP16(d, s, (n < NN) ? 16 : 0);
        }
        unsigned dw = smem_u32(&Ws[buf][wkk][wf4 * 4]);
        const float* sw = &W1[(size_t)(kc * 16 + wkk) * NH + wf4 * 4];
        CP16(dw, sw, 16);
        asm volatile("cp.async.commit_group;");
    };

    issue(0);
    for (int kc = 0; kc < NF / 16; kc++) {
        if (kc + 1 < NF / 16) {
            issue(kc + 1);
            asm volatile("cp.async.wait_group 1;");
        } else {
            asm volatile("cp.async.wait_group 0;");
        }
        __syncthreads();
        const int buf = kc & 1;

        #pragma unroll
        for (int kk = 0; kk < 16; kk++) {
            float av[8];
            #pragma unroll
            for (int i = 0; i < 8; i++) av[i] = Xs[buf][ty * 8 + i][kk];
            ulonglong2 w0 = *(const ulonglong2*)&Ws[buf][kk][tx * 8];
            ulonglong2 w1 = *(const ulonglong2*)&Ws[buf][kk][tx * 8 + 4];
            unsigned long long bp[4] = {w0.x, w0.y, w1.x, w1.y};
            #pragma unroll
            for (int i = 0; i < 8; i++) {
                unsigned long long ad;
                asm("mov.b64 %0, {%1, %1};" : "=l"(ad) : "f"(av[i]));
                #pragma unroll
                for (int jj = 0; jj < 4; jj++)
                    asm("fma.rn.f32x2 %0, %1, %2, %0;"
                        : "+l"(accp[i][jj]) : "l"(ad), "l"(bp[jj]));
            }
        }
        __syncthreads();
    }

    #pragma unroll
    for (int i = 0; i < 8; i++) {
        int n = n0 + ty * 8 + i;
        if (n < NN) {
            float s = rsqrtf((float)max(g_deg[n], 1));
            __half2 h[4];
            #pragma unroll
            for (int jj = 0; jj < 4; jj++) {
                float lo, hi;
                asm("mov.b64 {%0, %1}, %2;" : "=f"(lo), "=f"(hi) : "l"(accp[i][jj]));
                h[jj] = __floats2half2_rn(lo * s, hi * s);
            }
            *(uint4*)&g_h1h[(size_t)n * NH + tx * 8] = *(uint4*)h;
        }
    }
}

// ---------------- fused: gather1 + relu + hidden GEMM -> h2 ----------------
// 8 lanes/node x 8 halves (16B); 256 threads = 32 nodes/block; grid 3125 exact.
__global__ void __launch_bounds__(256) k_gather1h(const float* __restrict__ b1,
                                                  const float* __restrict__ W2) {
    __shared__ __align__(16) float Rs[32][NH];      // 8KB
    __shared__ __align__(16) float W2s[NH * NC];    // 4KB

    const int tid = threadIdx.x;
    const int nl = tid >> 3;                 // node local 0..31
    const int lane = tid & 7;
    const int g = blockIdx.x * 32 + nl;

    // load W2 into smem (1024 floats = 256 float4)
    *(float4*)&W2s[tid * 4] = *(const float4*)&W2[tid * 4];

    const int s0 = g_rowptr[g];
    const int s1 = g_rowptr[g + 1];
    float acc[8] = {};

    int j = s0;
    for (; j + 8 <= s1; j += 8) {
        int c[8];
        #pragma unroll
        for (int q = 0; q < 8; q++) c[q] = __ldg(&g_col[j + q]);
        #pragma unroll
        for (int q = 0; q < 8; q++) {
            uint4 v = *(const uint4*)&g_h1h[(size_t)c[q] * NH + lane * 8];
            const __half2* hv = (const __half2*)&v;
            #pragma unroll
            for (int p = 0; p < 4; p++) {
                float2 f = __half22float2(hv[p]);
                acc[2 * p] += f.x;
                acc[2 * p + 1] += f.y;
            }
        }
    }
    for (; j < s1; j++) {
        int c = __ldg(&g_col[j]);
        uint4 v = *(const uint4*)&g_h1h[(size_t)c * NH + lane * 8];
        const __half2* hv = (const __half2*)&v;
        #pragma unroll
        for (int p = 0; p < 4; p++) {
            float2 f = __half22float2(hv[p]);
            acc[2 * p] += f.x;
            acc[2 * p + 1] += f.y;
        }
    }

    // r = relu(acc*nd + b1) into smem
    float nd = rsqrtf((float)max(s1 - s0, 1));
    float4 bb0 = *(const float4*)&b1[lane * 8];
    float4 bb1 = *(const float4*)&b1[lane * 8 + 4];
    float bv[8] = {bb0.x, bb0.y, bb0.z, bb0.w, bb1.x, bb1.y, bb1.z, bb1.w};
    #pragma unroll
    for (int q = 0; q < 8; q++)
        Rs[nl][lane * 8 + q] = fmaxf(fmaf(acc[q], nd, bv[q]), 0.f);
    __syncthreads();

    // hidden GEMM: thread = (node nl, class pair lane*2, lane*2+1)
    const int c0 = lane * 2;
    float a0 = 0.f, a1 = 0.f;
    #pragma unroll
    for (int k = 0; k < NH; k++) {
        float rv = Rs[nl][k];
        float2 w = *(const float2*)&W2s[k * NC + c0];
        a0 = fmaf(rv, w.x, a0);
        a1 = fmaf(rv, w.y, a1);
    }
    float ns = rsqrtf((float)max(g_deg[g], 1));
    *(float2*)&g_h2[(size_t)g * NC + c0] = make_float2(a0 * ns, a1 * ns);
}

// ---------------- layer-2 gather + log_softmax fused ----------------
// 4 lanes/node, 1 float4 (4 classes) each; unroll 8.
__global__ void __launch_bounds__(256) k_gather2(const float* __restrict__ b2,
                                                 float* __restrict__ out) {
    int g0 = blockIdx.x * 64 + (threadIdx.x >> 2);
    const bool valid = (g0 < NN);
    const int g = valid ? g0 : (NN - 1);
    const int lane = threadIdx.x & 3;

    const int s0 = g_rowptr[g];
    const int s1 = g_rowptr[g + 1];
    unsigned long long acc0 = 0ull, acc1 = 0ull;

    int j = s0;
    for (; j + 8 <= s1; j += 8) {
        int c[8];
        #pragma unroll
        for (int q = 0; q < 8; q++) c[q] = __ldg(&g_col[j + q]);
        #pragma unroll
        for (int q = 0; q < 8; q++) {
            ulonglong2 v = *(const ulonglong2*)&g_h2[(size_t)c[q] * NC + lane * 4];
            ADD2(acc0, v.x);
            ADD2(acc1, v.y);
        }
    }
    for (; j < s1; j++) {
        int c = __ldg(&g_col[j]);
        ulonglong2 v = *(const ulonglong2*)&g_h2[(size_t)c * NC + lane * 4];
        ADD2(acc0, v.x);
        ADD2(acc1, v.y);
    }

    float nd = rsqrtf((float)max(s1 - s0, 1));
    float v[4];
    asm("mov.b64 {%0, %1}, %2;" : "=f"(v[0]), "=f"(v[1]) : "l"(acc0));
    asm("mov.b64 {%0, %1}, %2;" : "=f"(v[2]), "=f"(v[3]) : "l"(acc1));
    float4 bb = *(const float4*)&b2[lane * 4];
    v[0] = fmaf(v[0], nd, bb.x);
    v[1] = fmaf(v[1], nd, bb.y);
    v[2] = fmaf(v[2], nd, bb.z);
    v[3] = fmaf(v[3], nd, bb.w);

    float mloc = fmaxf(fmaxf(v[0], v[1]), fmaxf(v[2], v[3]));
    mloc = fmaxf(mloc, __shfl_xor_sync(0xFFFFFFFFu, mloc, 1, 4));
    mloc = fmaxf(mloc, __shfl_xor_sync(0xFFFFFFFFu, mloc, 2, 4));

    float sl = __expf(v[0] - mloc) + __expf(v[1] - mloc) +
               __expf(v[2] - mloc) + __expf(v[3] - mloc);
    sl += __shfl_xor_sync(0xFFFFFFFFu, sl, 1, 4);
    sl += __shfl_xor_sync(0xFFFFFFFFu, sl, 2, 4);
    float l = mloc + __logf(sl);

    if (valid)
        *(float4*)&out[(size_t)g * NC + lane * 4] =
            make_float4(v[0] - l, v[1] - l, v[2] - l, v[3] - l);
}

// ---------------- launch ----------------
extern "C" void kernel_launch(void* const* d_in, const int* in_sizes, int n_in,
                              void* d_out, int out_size) {
    const float* x   = (const float*)d_in[0];
    const int*   src = (const int*)d_in[1];
    const int*   dst = (const int*)d_in[2];
    const float* W1  = (const float*)d_in[3];
    const float* b1  = (const float*)d_in[4];
    const float* W2  = (const float*)d_in[5];
    const float* b2  = (const float*)d_in[6];
    float* out = (float*)d_out;

    void* pdeg;
    cudaGetSymbolAddress(&pdeg, g_deg);
    cudaMemsetAsync(pdeg, 0, (size_t)2 * NN * sizeof(int));

    k_hist<<<(NE + 255) / 256, 256>>>(dst);
    k_scanA<<<196, 256>>>();
    k_scanC<<<196, 256>>>();
    k_fill<<<(NE + 255) / 256, 256>>>(src, dst);
    k_gemm1<<<(NN + 255) / 256, 256>>>(x, W1);
    k_gather1h<<<NN / 32, 256>>>(b1, W2);
    k_gather2<<<(NN + 63) / 64, 256>>>(b2, out);
}